// round 4
// baseline (speedup 1.0000x reference)
#include <cuda_runtime.h>
#include <cstdint>
#include <math.h>

#define NVARS 1024
#define BATCH 64
#define KDIM  32
#define NIN   768
#define SWEEPS 10
#define PI_F 3.14159274101257324f

// ---------------- persistent scratch (no runtime allocation) ----------------
__device__ float V_g[BATCH * NVARS * KDIM];     // 8 MB
__device__ float v0_g[BATCH * KDIM];
__device__ unsigned short list_g[BATCH * NVARS];
__device__ int cnt_g[BATCH];

// ---------------- f32x2 helpers ----------------
__device__ __forceinline__ void ffma2(unsigned long long &d, unsigned long long a,
                                      unsigned long long b) {
    asm("fma.rn.f32x2 %0, %1, %2, %3;" : "=l"(d) : "l"(a), "l"(b), "l"(d));
}
__device__ __forceinline__ void fadd2(unsigned long long &d, unsigned long long a,
                                      unsigned long long b) {
    asm("add.rn.f32x2 %0, %1, %2;" : "=l"(d) : "l"(a), "l"(b));
}
__device__ __forceinline__ unsigned long long pk2(float lo, float hi) {
    unsigned long long r;
    asm("mov.b64 %0, {%1, %2};" : "=l"(r) : "f"(lo), "f"(hi));
    return r;
}
__device__ __forceinline__ void up2(unsigned long long v, float &lo, float &hi) {
    asm("mov.b64 {%0, %1}, %2;" : "=f"(lo), "=f"(hi) : "l"(v));
}

// ---------------- threefry2x32 core, exact JAX schedule ----------------
__device__ __forceinline__ void tf2x32(unsigned k0, unsigned k1,
                                       unsigned x0, unsigned x1,
                                       unsigned &y0, unsigned &y1) {
    unsigned ks2 = k0 ^ k1 ^ 0x1BD11BDAu;
    x0 += k0; x1 += k1;
#define TFR(r) { x0 += x1; x1 = (x1 << r) | (x1 >> (32 - r)); x1 ^= x0; }
    TFR(13) TFR(15) TFR(26) TFR(6)  x0 += k1;  x1 += ks2 + 1u;
    TFR(17) TFR(29) TFR(16) TFR(24) x0 += ks2; x1 += k0 + 2u;
    TFR(13) TFR(15) TFR(26) TFR(6)  x0 += k0;  x1 += k1 + 3u;
    TFR(17) TFR(29) TFR(16) TFR(24) x0 += k1;  x1 += ks2 + 4u;
    TFR(13) TFR(15) TFR(26) TFR(6)  x0 += ks2; x1 += k0 + 5u;
#undef TFR
    y0 = x0; y1 = x1;
}

// PARTITIONABLE threefry (modern JAX default):
//   split(key)[i]    = full output pair of tf2x32(key, hi=0, lo=i)
//   random_bits(e)   = y0 ^ y1 of tf2x32(key, hi=0, lo=e)     (sizes < 2^32)
__device__ __forceinline__ void derive_keys(unsigned &k1a, unsigned &k1b,
                                            unsigned &k2a, unsigned &k2b) {
    tf2x32(0u, 42u, 0u, 0u, k1a, k1b);   // subkey 0
    tf2x32(0u, 42u, 0u, 1u, k2a, k2b);   // subkey 1
}

__device__ __forceinline__ unsigned tf_bits(unsigned ka, unsigned kb, unsigned e) {
    unsigned y0, y1;
    tf2x32(ka, kb, 0u, e, y0, y1);
    return y0 ^ y1;
}

// bits -> N(0,1): uniform(nextafter(-1,0), 1) then sqrt(2)*erfinv (XLA f32 path).
// XLA emits separate mul/add HLO ops — use explicit rn intrinsics so nvcc
// cannot contract them into FFMA.
__device__ __forceinline__ float bits_to_normal(unsigned bits) {
    float u01 = __fadd_rn(__uint_as_float((bits >> 9) | 0x3F800000u), -1.0f);
    float u = __fadd_rn(__fmul_rn(u01, 2.0f), -0.99999994f);
    u = fmaxf(u, -0.99999994f);
    float x = u;
    float xx = __fmul_rn(x, x);
    float w = -log1pf(-xx);
    float p;
    if (w < 5.0f) {
        w = __fadd_rn(w, -2.5f);
        p = 2.81022636e-08f;
        p = __fadd_rn(__fmul_rn(p, w), 3.43273939e-07f);
        p = __fadd_rn(__fmul_rn(p, w), -3.5233877e-06f);
        p = __fadd_rn(__fmul_rn(p, w), -4.39150654e-06f);
        p = __fadd_rn(__fmul_rn(p, w), 0.00021858087f);
        p = __fadd_rn(__fmul_rn(p, w), -0.00125372503f);
        p = __fadd_rn(__fmul_rn(p, w), -0.00417768164f);
        p = __fadd_rn(__fmul_rn(p, w), 0.246640727f);
        p = __fadd_rn(__fmul_rn(p, w), 1.50140941f);
    } else {
        w = __fadd_rn(sqrtf(w), -3.0f);
        p = -0.000200214257f;
        p = __fadd_rn(__fmul_rn(p, w), 0.000100950558f);
        p = __fadd_rn(__fmul_rn(p, w), 0.00134934322f);
        p = __fadd_rn(__fmul_rn(p, w), -0.00367342844f);
        p = __fadd_rn(__fmul_rn(p, w), 0.00573950773f);
        p = __fadd_rn(__fmul_rn(p, w), -0.0076224613f);
        p = __fadd_rn(__fmul_rn(p, w), 0.00943887047f);
        p = __fadd_rn(__fmul_rn(p, w), 1.00167406f);
        p = __fadd_rn(__fmul_rn(p, w), 2.83297682f);
    }
    return __fmul_rn(1.41421354f, __fmul_rn(p, x));
}

__device__ __forceinline__ float warp_sum(float v) {
#pragma unroll
    for (int off = 16; off; off >>= 1)
        v += __shfl_xor_sync(0xffffffffu, v, off);
    return v;
}

// ---------------- kernel A: v0 (one warp per batch) ----------------
__global__ void v0_kernel() {
    int b = blockIdx.x;
    int l = threadIdx.x;
    unsigned k1a, k1b, k2a, k2b; derive_keys(k1a, k1b, k2a, k2b);
    unsigned e = (unsigned)(b * 32 + l);
    float n = bits_to_normal(tf_bits(k1a, k1b, e));
    float ss = warp_sum(__fmul_rn(n, n));
    v0_g[b * 32 + l] = n / sqrtf(ss);
}

// ---------------- kernel B: V init (one warp per (b,n)) ----------------
__global__ void initV_kernel(const float* __restrict__ z,
                             const int* __restrict__ is_input) {
    int gw = (blockIdx.x * blockDim.x + threadIdx.x) >> 5;
    int l = threadIdx.x & 31;
    int b = gw >> 10, n = gw & 1023;
    unsigned k1a, k1b, k2a, k2b; derive_keys(k1a, k1b, k2a, k2b);

    float v0l = v0_g[b * 32 + l];
    unsigned e = (unsigned)gw * 32u + (unsigned)l;
    float r = bits_to_normal(tf_bits(k2a, k2b, e));

    float d = warp_sum(__fmul_rn(r, v0l));
    float rp = __fadd_rn(r, -__fmul_rn(d, v0l));
    float nr = sqrtf(warp_sum(__fmul_rn(rp, rp)));
    float R = rp / nr;

    float zf; int ii;
    if (n == 0)        { zf = 1.0f; ii = 1; }
    else if (n <= NIN) { zf = z[b * NIN + n - 1]; ii = is_input[b * NIN + n - 1]; }
    else               { zf = 0.0f; ii = 0; }

    float V;
    if (ii > 0) {
        float x = __fmul_rn(PI_F, zf);
        V = __fadd_rn(__fmul_rn(-cosf(x), v0l), __fmul_rn(sinf(x), R));
    } else {
        V = R;
    }
    if (n == 0) V = v0l;
    V_g[gw * 32 + l] = V;
}

// ---------------- kernel C: per-batch free list (one warp per batch) ----------------
__global__ void freelist_kernel(const int* __restrict__ is_input) {
    int b = blockIdx.x;
    int l = threadIdx.x;
    int m = 0;
    for (int base = 1; base < 1024; base += 32) {
        int n = base + l;
        bool f = (n < 1024) && (n > NIN || is_input[b * NIN + n - 1] == 0);
        unsigned msk = __ballot_sync(0xffffffffu, f);
        if (f) {
            int pos = m + __popc(msk & ((1u << l) - 1u));
            list_g[b * 1024 + pos] = (unsigned short)n;
        }
        m += __popc(msk);
    }
    if (l == 0) cnt_g[b] = m;
}

// ---------------- kernel D: mixing solve + output (one CTA per batch) ----------------
__global__ void __launch_bounds__(512, 1)
mix_kernel(const float* __restrict__ C,
           const float* __restrict__ z,
           const int* __restrict__ is_input,
           float* __restrict__ out) {
    const int b = blockIdx.x;
    const int w = threadIdx.x >> 5;   // 16 warps, warp w owns rows [64w, 64w+64)
    const int l = threadIdx.x & 31;   // lane l holds column l

    __shared__ __align__(16) float pT[2][32 * 36];  // [buf][lane*36 + warp]
    __shared__ unsigned short lst[1024];
    __shared__ int scnt;

    for (int idx = threadIdx.x; idx < 1024; idx += 512)
        lst[idx] = list_g[b * 1024 + idx];
    if (threadIdx.x == 0) scnt = cnt_g[b];

    // V rows for this warp, packed as (row 2p, row 2p+1) f32x2 pairs
    unsigned long long v2[32];
#pragma unroll
    for (int p = 0; p < 32; p++) {
        int row = w * 64 + 2 * p;
        float a  = V_g[(b * 1024 + row) * 32 + l];
        float bb = V_g[(b * 1024 + row + 1) * 32 + l];
        v2[p] = pk2(a, bb);
    }
    __syncthreads();
    const int cnt = scnt;
    const int total = cnt * SWEEPS;

    int i_cur = lst[0];
    {
        const ulonglong2* Cp = reinterpret_cast<const ulonglong2*>(
            C + (size_t)i_cur * NVARS + w * 64);
        unsigned long long a0 = 0ull, a1 = 0ull, a2 = 0ull, a3 = 0ull;
#pragma unroll
        for (int q = 0; q < 16; q++) {
            ulonglong2 cc = Cp[q];
            ffma2(((q & 1) ? a2 : a0), cc.x, v2[2 * q]);
            ffma2(((q & 1) ? a3 : a1), cc.y, v2[2 * q + 1]);
        }
        fadd2(a0, a0, a2); fadd2(a1, a1, a3); fadd2(a0, a0, a1);
        float x, y; up2(a0, x, y);
        pT[0][l * 36 + w] = x + y;
    }

    for (int t = 0; t < total; t++) {
        __syncthreads();
        // reduce partials for coord i_cur
        const float4* pr = reinterpret_cast<const float4*>(&pT[t & 1][l * 36]);
        float4 r0 = pr[0], r1 = pr[1], r2 = pr[2], r3 = pr[3];
        float g = (((r0.x + r0.y) + (r0.z + r0.w)) + ((r1.x + r1.y) + (r1.z + r1.w)))
                + (((r2.x + r2.y) + (r2.z + r2.w)) + ((r3.x + r3.y) + (r3.z + r3.w)));
        float ss = warp_sum(g * g);
        float gn = fmaxf(sqrtf(ss), 1e-12f);
        float vn = -g / gn;

        // owner warp applies update to its private registers
        if (w == (i_cur >> 6)) {
            int j0 = i_cur & 63;
            int p0 = j0 >> 1;
#pragma unroll
            for (int p = 0; p < 32; p++)
                if (p == p0) {
                    float x, y; up2(v2[p], x, y);
                    if (j0 & 1) y = vn; else x = vn;
                    v2[p] = pk2(x, y);
                }
        }

        // dot for next coord into the other buffer
        if (t + 1 < total) {
            int m1 = t + 1;
            int mm = m1 - (m1 / cnt) * cnt;
            int i_nx = lst[mm];
            const ulonglong2* Cp = reinterpret_cast<const ulonglong2*>(
                C + (size_t)i_nx * NVARS + w * 64);
            unsigned long long a0 = 0ull, a1 = 0ull, a2 = 0ull, a3 = 0ull;
#pragma unroll
            for (int q = 0; q < 16; q++) {
                ulonglong2 cc = Cp[q];
                ffma2(((q & 1) ? a2 : a0), cc.x, v2[2 * q]);
                ffma2(((q & 1) ? a3 : a1), cc.y, v2[2 * q + 1]);
            }
            fadd2(a0, a0, a2); fadd2(a1, a1, a3); fadd2(a0, a0, a1);
            float x, y; up2(a0, x, y);
            pT[(t + 1) & 1][l * 36 + w] = x + y;
            i_cur = i_nx;
        }
    }

    // ---------------- epilogue: z_out[:, 1:769] ----------------
    float v0l = v0_g[b * 32 + l];
    const float CLO = (float)(-1.0 + 1e-7);
    const float CHI = (float)( 1.0 - 1e-7);
#pragma unroll
    for (int j = 0; j < 64; j++) {
        int n = w * 64 + j;
        if (n >= 1 && n <= NIN) {
            float x, y; up2(v2[j >> 1], x, y);
            float Vv = (j & 1) ? y : x;
            float d = warp_sum(__fmul_rn(Vv, v0l));
            if (l == 0) {
                int idx = b * NIN + n - 1;
                float res;
                if (is_input[idx] != 0) {
                    res = z[idx];
                } else {
                    float ca = fminf(fmaxf(-d, CLO), CHI);
                    res = acosf(ca) / PI_F;
                }
                out[idx] = res;
            }
        }
    }
}

// ---------------- launcher ----------------
extern "C" void kernel_launch(void* const* d_in, const int* in_sizes, int n_in,
                              void* d_out, int out_size) {
    const float* C        = (const float*)d_in[0];
    const float* z        = (const float*)d_in[1];
    const int*   is_input = (const int*)d_in[2];
    float* out = (float*)d_out;

    v0_kernel<<<BATCH, 32>>>();
    initV_kernel<<<(BATCH * NVARS) / 8, 256>>>(z, is_input);
    freelist_kernel<<<BATCH, 32>>>(is_input);
    mix_kernel<<<BATCH, 512>>>(C, z, is_input, out);
}